// round 16
// baseline (speedup 1.0000x reference)
#include <cuda_runtime.h>
#include <math.h>

#define NN 50000
#define TT 1000
#define KL 5
#define KR 15
#define NC 5
#define TWOPI 6.28318530717958647692f
#define PREG 98
#define PRETHR 512
#define GRIDF 296
#define MAXSLAB 169

typedef unsigned long long ull;

__device__ __forceinline__ ull pk2(float lo, float hi) {
    ull r; asm("mov.b64 %0,{%1,%2};" : "=l"(r) : "f"(lo), "f"(hi)); return r;
}
__device__ __forceinline__ ull ffma2(ull a, ull b, ull c) {
    ull d; asm("fma.rn.f32x2 %0,%1,%2,%3;" : "=l"(d) : "l"(a), "l"(b), "l"(c)); return d;
}

// per-block partial cluster sums: [count, sumAmp*4, sumCos*4, sumSin*4] x NC
__device__ float g_partial[PREG * 65];
// finalized cluster stats: [0..19] meanAmp, [20..39] circPhase, [40..44] big flag
__device__ float g_cmeans[48];
__device__ unsigned g_arr;  // arrival counter; reset by last block each launch

// ---------------------------------------------------------------------------
// Stage 1 (unchanged from R15): cluster partial sums via warp butterfly;
// last block finalizes with a parallel 7x65 reduction. Deterministic.
// ---------------------------------------------------------------------------
__global__ __launch_bounds__(PRETHR) void k_pre(const float4* __restrict__ amp,
                                                const float4* __restrict__ ph,
                                                const int* __restrict__ lab) {
    __shared__ float s_part[64 * 65];
    __shared__ float s_red[7 * 65];
    __shared__ float s_cl[65];
    __shared__ unsigned s_last;
    int tid = threadIdx.x;
    int wid = tid >> 5, lane = tid & 31;
    int n = blockIdx.x * PRETHR + tid;

    float v[13];
    int c = -1;
    if (n < NN) {
        float4 p = ph[n];
        float4 cs, sn;
        __sincosf(p.x, &sn.x, &cs.x);
        __sincosf(p.y, &sn.y, &cs.y);
        __sincosf(p.z, &sn.z, &cs.z);
        __sincosf(p.w, &sn.w, &cs.w);
        float4 a = amp[n];
        c = lab[n];
        v[0] = 1.f;
        v[1] = a.x;  v[2] = a.y;  v[3] = a.z;  v[4] = a.w;
        v[5] = cs.x; v[6] = cs.y; v[7] = cs.z; v[8] = cs.w;
        v[9] = sn.x; v[10] = sn.y; v[11] = sn.z; v[12] = sn.w;
    } else {
        #pragma unroll
        for (int i = 0; i < 13; i++) v[i] = 0.f;
    }

    #pragma unroll
    for (int cc = 0; cc < NC; cc++) {
        #pragma unroll
        for (int i = 0; i < 13; i++) {
            float x = (c == cc) ? v[i] : 0.f;
            x += __shfl_xor_sync(0xffffffffu, x, 16);
            x += __shfl_xor_sync(0xffffffffu, x, 8);
            x += __shfl_xor_sync(0xffffffffu, x, 4);
            if (lane < 4) s_part[(wid * 4 + lane) * 65 + cc * 13 + i] = x;
        }
    }
    __syncthreads();
    if (tid < 65) {
        float s = 0.f;
        #pragma unroll
        for (int w = 0; w < 64; w++) s += s_part[w * 65 + tid];
        g_partial[blockIdx.x * 65 + tid] = s;
    }
    __threadfence();
    __syncthreads();
    if (tid == 0) {
        unsigned o = atomicAdd(&g_arr, 1u);
        s_last = (o == PREG - 1) ? 1u : 0u;
    }
    __syncthreads();
    if (s_last) {
        __threadfence();
        if (tid < 7 * 65) {
            int g = tid / 65, vv = tid - g * 65;
            float s = 0.f;
            for (int r = g; r < PREG; r += 7) s += g_partial[r * 65 + vv];
            s_red[g * 65 + vv] = s;
        }
        __syncthreads();
        if (tid < 65) {
            float s = 0.f;
            #pragma unroll
            for (int g = 0; g < 7; g++) s += s_red[g * 65 + tid];
            s_cl[tid] = s;
        }
        __syncthreads();
        if (tid < 20) {
            int cc = tid >> 2, i = tid & 3;
            float cnt = s_cl[cc * 13];
            g_cmeans[tid]      = s_cl[cc * 13 + 1 + i] / fmaxf(cnt, 1.f);
            g_cmeans[20 + tid] = atan2f(s_cl[cc * 13 + 9 + i], s_cl[cc * 13 + 5 + i]);
            if (i == 0) g_cmeans[40 + cc] = (cnt > 1.f) ? 1.f : 0.f;
        }
        if (tid == 0) g_arr = 0u;   // reset for next graph replay
    }
}

// Accumulate up to 8 neighbors with ALL loads batched (up to 16 LDG.128
// issued back-to-back -> ONE L2 round trip per role).
__device__ __forceinline__ void accumN(const float4* __restrict__ ampP,
                                       const float4* __restrict__ phP,
                                       const int* jj, const float* ww, int cnt,
                                       float* sa, float* sc, float* ss) {
    float4 aj[8], pj[8];
    #pragma unroll
    for (int k = 0; k < 8; k++) {
        if (k < cnt) { aj[k] = ampP[jj[k]]; pj[k] = phP[jj[k]]; }
    }
    #pragma unroll
    for (int k = 0; k < 8; k++) {
        if (k < cnt) {
            float w = ww[k];
            float c0, s0, c1, s1, c2, s2, c3, s3;
            __sincosf(pj[k].x, &s0, &c0);
            __sincosf(pj[k].y, &s1, &c1);
            __sincosf(pj[k].z, &s2, &c2);
            __sincosf(pj[k].w, &s3, &c3);
            sa[0] = fmaf(aj[k].x, w, sa[0]); sa[1] = fmaf(aj[k].y, w, sa[1]);
            sa[2] = fmaf(aj[k].z, w, sa[2]); sa[3] = fmaf(aj[k].w, w, sa[3]);
            sc[0] = fmaf(c0, w, sc[0]); sc[1] = fmaf(c1, w, sc[1]);
            sc[2] = fmaf(c2, w, sc[2]); sc[3] = fmaf(c3, w, sc[3]);
            ss[0] = fmaf(s0, w, ss[0]); ss[1] = fmaf(s1, w, ss[1]);
            ss[2] = fmaf(s2, w, ss[2]); ss[3] = fmaf(s3, w, ss[3]);
        }
    }
}

// ---------------------------------------------------------------------------
// Stage 2 (fused coef + fill). 2 blocks/SM -> ~128 regs -> whole-role load
// batching (one L2 round trip per role) + balanced 2-pass role loop
// (3*169=507 units over 256 threads: 100%/98% occupancy).
// ---------------------------------------------------------------------------
__global__ __launch_bounds__(256, 2) void k_fused(const float* __restrict__ tv,
                                                  const float* __restrict__ co,
                                                  const float* __restrict__ lt,
                                                  const float* __restrict__ amp,
                                                  const float* __restrict__ ph,
                                                  const float* __restrict__ lw,
                                                  const float* __restrict__ rw,
                                                  const int* __restrict__ li,
                                                  const int* __restrict__ ri,
                                                  const int* __restrict__ lab,
                                                  float* __restrict__ out) {
    __shared__ float s_cm[48];
    __shared__ float s_pp[MAXSLAB * 36];     // 3 chunks x 12 floats per node
    __shared__ ulonglong2 s_cp[MAXSLAB * 5]; // dup-packed coefficients
    int tid = threadIdx.x;
    int start = (int)(((long long)blockIdx.x * NN) / GRIDF);
    int end   = (int)(((long long)(blockIdx.x + 1) * NN) / GRIDF);
    int nn = end - start;

    if (tid < 48) s_cm[tid] = g_cmeans[tid];

    const float4* ampP = (const float4*)amp;
    const float4* phP  = (const float4*)ph;

    // phase A: gather, 3 roles per node (local | regional 0-7 | regional 8-14)
    for (int i = tid; i < 3 * nn; i += 256) {
        int chunk = i / nn, node = i - chunk * nn;
        int gn = start + node;
        float sa[4] = {0,0,0,0}, sc[4] = {0,0,0,0}, ss[4] = {0,0,0,0};
        if (chunk == 0) {
            int jj[8]; float ww[8];
            #pragma unroll
            for (int k = 0; k < KL; k++) {
                jj[k] = li[gn * KL + k];
                ww[k] = lw[gn * KL + k];
            }
            accumN(ampP, phP, jj, ww, KL, sa, sc, ss);
        } else {
            int kb = (chunk == 1) ? 0 : 8;
            int cntk = (chunk == 1) ? 8 : 7;
            int jj[8]; float ww[8];
            #pragma unroll
            for (int k = 0; k < 8; k++) {
                if (k < cntk) {
                    jj[k] = ri[gn * KR + kb + k];
                    ww[k] = rw[gn * KR + kb + k];
                }
            }
            accumN(ampP, phP, jj, ww, cntk, sa, sc, ss);
        }
        float* dst = &s_pp[node * 36 + chunk * 12];
        #pragma unroll
        for (int k = 0; k < 4; k++) {
            dst[k] = sa[k]; dst[4 + k] = sc[k]; dst[8 + k] = ss[k];
        }
    }
    __syncthreads();

    // phase B: coefficients
    for (int node = tid; node < nn; node += 256) {
        int gn = start + node;
        const float* p0 = &s_pp[node * 36];
        const float* p1 = p0 + 12;
        const float* p2 = p0 + 24;
        float4 a4 = ampP[gn];
        float4 p4 = phP[gn];
        float cov = co[gn], ltv = lt[gn];
        int c = lab[gn];
        bool big = s_cm[40 + c] > 0.5f;
        float aP[4] = {a4.x, a4.y, a4.z, a4.w};
        float pP[4] = {p4.x, p4.y, p4.z, p4.w};
        float av[4], bv[4];
        #pragma unroll
        for (int i = 0; i < 4; i++) {
            float ra = p1[i] + p2[i];
            float rc = p1[4 + i] + p2[4 + i];
            float rs = p1[8 + i] + p2[8 + i];
            float campU = big ? s_cm[c * 4 + i] : aP[i];
            // combined = 0.5*local + 0.3*(0.7*regional_sum) + 0.2*cluster
            float ampO = 0.7f * aP[i] + 0.3f * (0.5f * p0[i] + 0.21f * ra + 0.2f * campU);
            float cphU = big ? s_cm[20 + c * 4 + i] : pP[i];
            float phL = atan2f(p0[8 + i], p0[4 + i]);
            float phR = atan2f(rs, rc);
            float phO = 0.7f * pP[i] + 0.3f * (0.5f * phL + 0.3f * phR + 0.2f * cphU);
            float s, cc2;
            __sincosf(phO, &s, &cc2);
            av[i] = ampO * cc2;
            bv[i] = ampO * s;
        }
        ull* q = (ull*)&s_cp[node * 5];
        q[0] = pk2(cov, cov);     q[1] = pk2(ltv, ltv);
        q[2] = pk2(av[0], av[0]); q[3] = pk2(av[1], av[1]);
        q[4] = pk2(av[2], av[2]); q[5] = pk2(av[3], av[3]);
        q[6] = pk2(bv[0], bv[0]); q[7] = pk2(bv[1], bv[1]);
        q[8] = pk2(bv[2], bv[2]); q[9] = pk2(bv[3], bv[3]);
    }
    __syncthreads();

    int t0 = tid * 4;
    if (t0 >= TT) return;  // threads 250..255 already did their shared-memory duty

    float4 tvv = ((const float4*)tv)[tid];
    ull T01 = pk2(tvv.x, tvv.y);
    ull T23 = pk2(tvv.z, tvv.w);

    const float w[4] = {TWOPI * 4.f, TWOPI * 2.f, TWOPI, TWOPI * 0.5f};
    ull S01[4], C01[4], S23[4], C23[4];
    #pragma unroll
    for (int i = 0; i < 4; i++) {
        float s0, c0, s1, c1, s2, c2, s3, c3;
        sincosf(w[i] * tvv.x, &s0, &c0);
        sincosf(w[i] * tvv.y, &s1, &c1);
        sincosf(w[i] * tvv.z, &s2, &c2);
        sincosf(w[i] * tvv.w, &s3, &c3);
        S01[i] = pk2(s0, s1); C01[i] = pk2(c0, c1);
        S23[i] = pk2(s2, s3); C23[i] = pk2(c2, c3);
    }

    #pragma unroll 2
    for (int j = 0; j < nn; j++) {
        ulonglong2 e0 = s_cp[j * 5 + 0];
        ulonglong2 e1 = s_cp[j * 5 + 1];
        ulonglong2 e2 = s_cp[j * 5 + 2];
        ulonglong2 e3 = s_cp[j * 5 + 3];
        ulonglong2 e4 = s_cp[j * 5 + 4];
        ull r0 = ffma2(e0.y, T01, e0.x);
        r0 = ffma2(e1.x, S01[0], r0); r0 = ffma2(e1.y, S01[1], r0);
        r0 = ffma2(e2.x, S01[2], r0); r0 = ffma2(e2.y, S01[3], r0);
        r0 = ffma2(e3.x, C01[0], r0); r0 = ffma2(e3.y, C01[1], r0);
        r0 = ffma2(e4.x, C01[2], r0); r0 = ffma2(e4.y, C01[3], r0);
        ull r1 = ffma2(e0.y, T23, e0.x);
        r1 = ffma2(e1.x, S23[0], r1); r1 = ffma2(e1.y, S23[1], r1);
        r1 = ffma2(e2.x, S23[2], r1); r1 = ffma2(e2.y, S23[3], r1);
        r1 = ffma2(e3.x, C23[0], r1); r1 = ffma2(e3.y, C23[1], r1);
        r1 = ffma2(e4.x, C23[2], r1); r1 = ffma2(e4.y, C23[3], r1);
        longlong2 o;
        o.x = (long long)r0; o.y = (long long)r1;
        __stcs(reinterpret_cast<longlong2*>(out + (size_t)(start + j) * TT + t0), o);
    }
}

extern "C" void kernel_launch(void* const* d_in, const int* in_sizes, int n_in,
                              void* d_out, int out_size) {
    const float* tv  = (const float*)d_in[0];  // time_vector        [1000]
    const float* co  = (const float*)d_in[1];  // constant_offset    [50000]
    const float* lt  = (const float*)d_in[2];  // linear_trend       [50000]
    const float* amp = (const float*)d_in[3];  // seasonal_amplitudes[50000,4]
    const float* ph  = (const float*)d_in[4];  // seasonal_phases    [50000,4]
    const float* lw  = (const float*)d_in[5];  // local_w            [50000,5]
    const float* rw  = (const float*)d_in[6];  // regional_w         [50000,15]
    const int*   li  = (const int*)d_in[7];    // local_idx          [50000,5]
    const int*   ri  = (const int*)d_in[8];    // regional_idx       [50000,15]
    const int*   lab = (const int*)d_in[9];    // cluster_labels     [50000]
    float* out = (float*)d_out;

    k_pre<<<PREG, PRETHR>>>((const float4*)amp, (const float4*)ph, lab);
    k_fused<<<GRIDF, 256>>>(tv, co, lt, amp, ph, lw, rw, li, ri, lab, out);
}

// round 17
// speedup vs baseline: 1.0498x; 1.0498x over previous
#include <cuda_runtime.h>
#include <math.h>

#define NN 50000
#define TT 1000
#define KL 5
#define KR 15
#define NC 5
#define TWOPI 6.28318530717958647692f
#define GRIDF 296
#define MAXSLAB 169

typedef unsigned long long ull;

__device__ __forceinline__ ull pk2(float lo, float hi) {
    ull r; asm("mov.b64 %0,{%1,%2};" : "=l"(r) : "f"(lo), "f"(hi)); return r;
}
__device__ __forceinline__ ull ffma2(ull a, ull b, ull c) {
    ull d; asm("fma.rn.f32x2 %0,%1,%2,%3;" : "=l"(d) : "l"(a), "l"(b), "l"(c)); return d;
}

// per-block partial cluster sums: [count, sumAmp*4, sumCos*4, sumSin*4] x NC
__device__ float g_partial[GRIDF * 65];
// finalized cluster stats: [0..19] meanAmp, [20..39] circPhase, [40..44] big flag
__device__ float g_cmeans[48];
__device__ unsigned g_cnt;            // arrival counter; reset before release
__device__ volatile unsigned g_flag;  // monotonic release ticket

// Accumulate up to 8 neighbors with ALL loads batched (up to 16 LDG.128
// issued back-to-back -> ONE L2 round trip per role).
__device__ __forceinline__ void accumN(const float4* __restrict__ ampP,
                                       const float4* __restrict__ phP,
                                       const int* jj, const float* ww, int cnt,
                                       float* sa, float* sc, float* ss) {
    float4 aj[8], pj[8];
    #pragma unroll
    for (int k = 0; k < 8; k++) {
        if (k < cnt) { aj[k] = ampP[jj[k]]; pj[k] = phP[jj[k]]; }
    }
    #pragma unroll
    for (int k = 0; k < 8; k++) {
        if (k < cnt) {
            float w = ww[k];
            float c0, s0, c1, s1, c2, s2, c3, s3;
            __sincosf(pj[k].x, &s0, &c0);
            __sincosf(pj[k].y, &s1, &c1);
            __sincosf(pj[k].z, &s2, &c2);
            __sincosf(pj[k].w, &s3, &c3);
            sa[0] = fmaf(aj[k].x, w, sa[0]); sa[1] = fmaf(aj[k].y, w, sa[1]);
            sa[2] = fmaf(aj[k].z, w, sa[2]); sa[3] = fmaf(aj[k].w, w, sa[3]);
            sc[0] = fmaf(c0, w, sc[0]); sc[1] = fmaf(c1, w, sc[1]);
            sc[2] = fmaf(c2, w, sc[2]); sc[3] = fmaf(c3, w, sc[3]);
            ss[0] = fmaf(s0, w, ss[0]); ss[1] = fmaf(s1, w, ss[1]);
            ss[2] = fmaf(s2, w, ss[2]); ss[3] = fmaf(s3, w, ss[3]);
        }
    }
}

// ---------------------------------------------------------------------------
// Single kernel. 296 blocks = 148 SMs x 2 (exactly one co-resident wave;
// required for the ticket release below).
//  P: per-slab cluster butterfly -> partial; last arrival reduces -> g_cmeans
//     and bumps the ticket. NO block waits here.
//  A: gather (independent of cluster means -> overlaps the reduction).
//  wait: check ticket (normally already set), then load g_cmeans.
//  B: coefficients.  C: 200MB fill (f32x2 chain, streaming stores).
// ---------------------------------------------------------------------------
__global__ __launch_bounds__(256, 2) void k_all(const float* __restrict__ tv,
                                                const float* __restrict__ co,
                                                const float* __restrict__ lt,
                                                const float* __restrict__ amp,
                                                const float* __restrict__ ph,
                                                const float* __restrict__ lw,
                                                const float* __restrict__ rw,
                                                const int* __restrict__ li,
                                                const int* __restrict__ ri,
                                                const int* __restrict__ lab,
                                                float* __restrict__ out) {
    __shared__ float s_part[32 * 65];        // 8 warps x 4 residue rows
    __shared__ float s_red[3 * 65];
    __shared__ float s_cl[65];
    __shared__ float s_cm[48];
    __shared__ float s_pp[MAXSLAB * 36];     // 3 chunks x 12 floats per node
    __shared__ ulonglong2 s_cp[MAXSLAB * 5]; // dup-packed coefficients
    __shared__ unsigned s_last;

    int tid = threadIdx.x, bid = blockIdx.x;
    int wid = tid >> 5, lane = tid & 31;
    int start = (int)(((long long)bid * NN) / GRIDF);
    int end   = (int)(((long long)(bid + 1) * NN) / GRIDF);
    int nn = end - start;

    const float4* ampP = (const float4*)amp;
    const float4* phP  = (const float4*)ph;

    // ---- phase P: slab cluster partials (3-step warp butterfly) ----
    {
        float v[13];
        int c = -1;
        if (tid < nn) {
            int gn = start + tid;
            float4 p = phP[gn];
            float4 a = ampP[gn];
            float4 cs, sn;
            __sincosf(p.x, &sn.x, &cs.x);
            __sincosf(p.y, &sn.y, &cs.y);
            __sincosf(p.z, &sn.z, &cs.z);
            __sincosf(p.w, &sn.w, &cs.w);
            c = lab[gn];
            v[0] = 1.f;
            v[1] = a.x;  v[2] = a.y;  v[3] = a.z;  v[4] = a.w;
            v[5] = cs.x; v[6] = cs.y; v[7] = cs.z; v[8] = cs.w;
            v[9] = sn.x; v[10] = sn.y; v[11] = sn.z; v[12] = sn.w;
        } else {
            #pragma unroll
            for (int i = 0; i < 13; i++) v[i] = 0.f;
        }
        #pragma unroll
        for (int cc = 0; cc < NC; cc++) {
            #pragma unroll
            for (int i = 0; i < 13; i++) {
                float x = (c == cc) ? v[i] : 0.f;
                x += __shfl_xor_sync(0xffffffffu, x, 16);
                x += __shfl_xor_sync(0xffffffffu, x, 8);
                x += __shfl_xor_sync(0xffffffffu, x, 4);
                if (lane < 4) s_part[(wid * 4 + lane) * 65 + cc * 13 + i] = x;
            }
        }
        __syncthreads();
        if (tid < 65) {
            float s = 0.f;
            #pragma unroll
            for (int w = 0; w < 32; w++) s += s_part[w * 65 + tid];
            g_partial[bid * 65 + tid] = s;
        }
        __threadfence();
        __syncthreads();
    }

    // ---- arrival; last block reduces and releases the ticket ----
    unsigned tick = 0;
    if (tid == 0) {
        tick = g_flag;
        unsigned o = atomicAdd(&g_cnt, 1u);
        s_last = (o == (unsigned)(GRIDF - 1)) ? 1u : 0u;
    }
    __syncthreads();
    if (s_last) {
        __threadfence();
        if (tid < 3 * 65) {
            int g = tid / 65, vv = tid - g * 65;
            float s = 0.f;
            for (int r = g; r < GRIDF; r += 3) s += g_partial[r * 65 + vv];
            s_red[g * 65 + vv] = s;
        }
        __syncthreads();
        if (tid < 65) s_cl[tid] = s_red[tid] + s_red[65 + tid] + s_red[130 + tid];
        __syncthreads();
        if (tid < 20) {
            int cc = tid >> 2, i = tid & 3;
            float cnt = s_cl[cc * 13];
            g_cmeans[tid]      = s_cl[cc * 13 + 1 + i] / fmaxf(cnt, 1.f);
            g_cmeans[20 + tid] = atan2f(s_cl[cc * 13 + 9 + i], s_cl[cc * 13 + 5 + i]);
            if (i == 0) g_cmeans[40 + cc] = (cnt > 1.f) ? 1.f : 0.f;
        }
        __threadfence();
        __syncthreads();
        if (tid == 0) {
            g_cnt = 0;                    // reset for next launch/replay
            __threadfence();
            atomicAdd((unsigned*)&g_flag, 1u);
        }
    }

    // ---- phase A: gather (independent of cluster means) ----
    for (int i = tid; i < 3 * nn; i += 256) {
        int chunk = i / nn, node = i - chunk * nn;
        int gn = start + node;
        float sa[4] = {0,0,0,0}, sc[4] = {0,0,0,0}, ss[4] = {0,0,0,0};
        if (chunk == 0) {
            int jj[8]; float ww[8];
            #pragma unroll
            for (int k = 0; k < KL; k++) {
                jj[k] = li[gn * KL + k];
                ww[k] = lw[gn * KL + k];
            }
            accumN(ampP, phP, jj, ww, KL, sa, sc, ss);
        } else {
            int kb = (chunk == 1) ? 0 : 8;
            int cntk = (chunk == 1) ? 8 : 7;
            int jj[8]; float ww[8];
            #pragma unroll
            for (int k = 0; k < 8; k++) {
                if (k < cntk) {
                    jj[k] = ri[gn * KR + kb + k];
                    ww[k] = rw[gn * KR + kb + k];
                }
            }
            accumN(ampP, phP, jj, ww, cntk, sa, sc, ss);
        }
        float* dst = &s_pp[node * 36 + chunk * 12];
        #pragma unroll
        for (int k = 0; k < 4; k++) {
            dst[k] = sa[k]; dst[4 + k] = sc[k]; dst[8 + k] = ss[k];
        }
    }

    // ---- ticket check (normally already released), then load cmeans ----
    if (!s_last) {
        if (tid == 0) {
            while (g_flag == tick) __nanosleep(32);
        }
    }
    __syncthreads();
    __threadfence();
    if (tid < 48) s_cm[tid] = g_cmeans[tid];
    __syncthreads();

    // ---- phase B: coefficients ----
    for (int node = tid; node < nn; node += 256) {
        int gn = start + node;
        const float* p0 = &s_pp[node * 36];
        const float* p1 = p0 + 12;
        const float* p2 = p0 + 24;
        float4 a4 = ampP[gn];
        float4 p4 = phP[gn];
        float cov = co[gn], ltv = lt[gn];
        int c = lab[gn];
        bool big = s_cm[40 + c] > 0.5f;
        float aP[4] = {a4.x, a4.y, a4.z, a4.w};
        float pP[4] = {p4.x, p4.y, p4.z, p4.w};
        float av[4], bv[4];
        #pragma unroll
        for (int i = 0; i < 4; i++) {
            float ra = p1[i] + p2[i];
            float rc = p1[4 + i] + p2[4 + i];
            float rs = p1[8 + i] + p2[8 + i];
            float campU = big ? s_cm[c * 4 + i] : aP[i];
            // combined = 0.5*local + 0.3*(0.7*regional_sum) + 0.2*cluster
            float ampO = 0.7f * aP[i] + 0.3f * (0.5f * p0[i] + 0.21f * ra + 0.2f * campU);
            float cphU = big ? s_cm[20 + c * 4 + i] : pP[i];
            float phL = atan2f(p0[8 + i], p0[4 + i]);
            float phR = atan2f(rs, rc);
            float phO = 0.7f * pP[i] + 0.3f * (0.5f * phL + 0.3f * phR + 0.2f * cphU);
            float s, cc2;
            __sincosf(phO, &s, &cc2);
            av[i] = ampO * cc2;
            bv[i] = ampO * s;
        }
        ull* q = (ull*)&s_cp[node * 5];
        q[0] = pk2(cov, cov);     q[1] = pk2(ltv, ltv);
        q[2] = pk2(av[0], av[0]); q[3] = pk2(av[1], av[1]);
        q[4] = pk2(av[2], av[2]); q[5] = pk2(av[3], av[3]);
        q[6] = pk2(bv[0], bv[0]); q[7] = pk2(bv[1], bv[1]);
        q[8] = pk2(bv[2], bv[2]); q[9] = pk2(bv[3], bv[3]);
    }
    __syncthreads();

    // ---- phase C: fill ----
    int t0 = tid * 4;
    if (t0 >= TT) return;  // threads 250..255 already did their shared-memory duty

    float4 tvv = ((const float4*)tv)[tid];
    ull T01 = pk2(tvv.x, tvv.y);
    ull T23 = pk2(tvv.z, tvv.w);

    const float w[4] = {TWOPI * 4.f, TWOPI * 2.f, TWOPI, TWOPI * 0.5f};
    ull S01[4], C01[4], S23[4], C23[4];
    #pragma unroll
    for (int i = 0; i < 4; i++) {
        float s0, c0, s1, c1, s2, c2, s3, c3;
        sincosf(w[i] * tvv.x, &s0, &c0);
        sincosf(w[i] * tvv.y, &s1, &c1);
        sincosf(w[i] * tvv.z, &s2, &c2);
        sincosf(w[i] * tvv.w, &s3, &c3);
        S01[i] = pk2(s0, s1); C01[i] = pk2(c0, c1);
        S23[i] = pk2(s2, s3); C23[i] = pk2(c2, c3);
    }

    #pragma unroll 2
    for (int j = 0; j < nn; j++) {
        ulonglong2 e0 = s_cp[j * 5 + 0];
        ulonglong2 e1 = s_cp[j * 5 + 1];
        ulonglong2 e2 = s_cp[j * 5 + 2];
        ulonglong2 e3 = s_cp[j * 5 + 3];
        ulonglong2 e4 = s_cp[j * 5 + 4];
        ull r0 = ffma2(e0.y, T01, e0.x);
        r0 = ffma2(e1.x, S01[0], r0); r0 = ffma2(e1.y, S01[1], r0);
        r0 = ffma2(e2.x, S01[2], r0); r0 = ffma2(e2.y, S01[3], r0);
        r0 = ffma2(e3.x, C01[0], r0); r0 = ffma2(e3.y, C01[1], r0);
        r0 = ffma2(e4.x, C01[2], r0); r0 = ffma2(e4.y, C01[3], r0);
        ull r1 = ffma2(e0.y, T23, e0.x);
        r1 = ffma2(e1.x, S23[0], r1); r1 = ffma2(e1.y, S23[1], r1);
        r1 = ffma2(e2.x, S23[2], r1); r1 = ffma2(e2.y, S23[3], r1);
        r1 = ffma2(e3.x, C23[0], r1); r1 = ffma2(e3.y, C23[1], r1);
        r1 = ffma2(e4.x, C23[2], r1); r1 = ffma2(e4.y, C23[3], r1);
        longlong2 o;
        o.x = (long long)r0; o.y = (long long)r1;
        __stcs(reinterpret_cast<longlong2*>(out + (size_t)(start + j) * TT + t0), o);
    }
}

extern "C" void kernel_launch(void* const* d_in, const int* in_sizes, int n_in,
                              void* d_out, int out_size) {
    const float* tv  = (const float*)d_in[0];  // time_vector        [1000]
    const float* co  = (const float*)d_in[1];  // constant_offset    [50000]
    const float* lt  = (const float*)d_in[2];  // linear_trend       [50000]
    const float* amp = (const float*)d_in[3];  // seasonal_amplitudes[50000,4]
    const float* ph  = (const float*)d_in[4];  // seasonal_phases    [50000,4]
    const float* lw  = (const float*)d_in[5];  // local_w            [50000,5]
    const float* rw  = (const float*)d_in[6];  // regional_w         [50000,15]
    const int*   li  = (const int*)d_in[7];    // local_idx          [50000,5]
    const int*   ri  = (const int*)d_in[8];    // regional_idx       [50000,15]
    const int*   lab = (const int*)d_in[9];    // cluster_labels     [50000]
    float* out = (float*)d_out;

    k_all<<<GRIDF, 256>>>(tv, co, lt, amp, ph, lw, rw, li, ri, lab, out);
}